// round 7
// baseline (speedup 1.0000x reference)
#include <cuda_runtime.h>
#include <math.h>
#include <stdint.h>

// Problem constants (match reference setup_inputs)
#define DIMF     2048
#define KIDS     8
#define P        256
#define HALF     2048
#define MARGIN   1.0f

#define GRID     128                   // 2 identities per CTA
#define THREADS  256
#define GROUP    16
// Buffer = 8 rows (one identity half), staged as 4 pair-copies of 16KB.
// Pair stride padded +16B so row bank-shift = 4 banks per pair.
#define PAIR_BYTES   (2 * DIMF * 4 + 16)      // 16400
#define BUF_BYTES    (4 * PAIR_BYTES)          // 65600
#define NBUF     3
#define SMEM_BYTES   (NBUF * BUF_BYTES)        // 196800

// D(16x8) += A(16x8) * B(8x8), tf32. Gram trick: B fragments are A fragments.
#define MMA_TF32(d, a0, a1, a2, a3, b0, b1)                                \
    asm volatile(                                                          \
        "mma.sync.aligned.m16n8k8.row.col.f32.tf32.tf32.f32 "              \
        "{%0,%1,%2,%3}, {%4,%5,%6,%7}, {%8,%9}, {%0,%1,%2,%3};"            \
        : "+f"(d[0]), "+f"(d[1]), "+f"(d[2]), "+f"(d[3])                   \
        : "r"(a0), "r"(a1), "r"(a2), "r"(a3), "r"(b0), "r"(b1))

__device__ __forceinline__ uint32_t smem_u32(const void* p) {
    return (uint32_t)__cvta_generic_to_shared(p);
}
__device__ __forceinline__ void mbar_wait(uint32_t mbar, uint32_t parity) {
    asm volatile(
        "{\n\t.reg .pred P1;\n\t"
        "LAB_WAIT_%=:\n\t"
        "mbarrier.try_wait.parity.acquire.cta.shared::cta.b64 P1, [%0], %1, 0x989680;\n\t"
        "@P1 bra.uni LAB_DONE_%=;\n\t"
        "bra.uni LAB_WAIT_%=;\n\t"
        "LAB_DONE_%=:\n\t}"
        :: "r"(mbar), "r"(parity) : "memory");
}

// buffer-local float offset of row r (0..7)
__device__ __forceinline__ int foff(int r) {
    return (r >> 1) * (PAIR_BYTES / 4) + (r & 1) * DIMF;
}

__global__ __launch_bounds__(THREADS, 1)
void wloss_kernel(const float* __restrict__ x, float* __restrict__ out)
{
    extern __shared__ float smf[];               // [NBUF][BUF]
    __shared__ float    gramA[GROUP][GROUP];
    __shared__ float    gramB[GROUP][GROUP];
    __shared__ uint64_t s_mbar[NBUF];

    const int tid  = threadIdx.x;
    const int w    = tid >> 5;                   // warp 0..7 (K split)
    const int lane = tid & 31;
    const int p0   = blockIdx.x * 2;             // identities p0, p0+1
    const int p1   = p0 + 1;

    const uint32_t smbase = smem_u32(smf);
    const uint32_t mbb    = smem_u32(&s_mbar[0]);

    // zero gram tables (512 floats, 256 threads)
    ((float*)gramA)[tid] = 0.0f;
    ((float*)gramB)[tid] = 0.0f;
    if (tid == 0) {
        #pragma unroll
        for (int b = 0; b < NBUF; b++)
            asm volatile("mbarrier.init.shared.b64 [%0], 1;"
                         :: "r"(mbb + 8u * b) : "memory");
    }
    __syncthreads();

    // stage identity-half (p, h) into buffer b: 4 bulk copies of 16KB
    auto stage = [&](int p, int h, int b) {
        uint32_t mb = mbb + 8u * b;
        asm volatile("mbarrier.arrive.expect_tx.shared.b64 _, [%0], %1;"
                     :: "r"(mb), "r"((uint32_t)(KIDS * DIMF * 4)) : "memory");
        int baserow = (h == 0) ? (p * KIDS) : (HALF + p * KIDS);
        #pragma unroll
        for (int q = 0; q < 4; q++) {
            const float* src = x + (size_t)(baserow + 2 * q) * DIMF;
            uint32_t dst = smbase + (uint32_t)(b * BUF_BYTES + q * PAIR_BYTES);
            asm volatile(
                "cp.async.bulk.shared::cluster.global.mbarrier::complete_tx::bytes "
                "[%0], [%1], %2, [%3];"
                :: "r"(dst), "l"(src), "r"((uint32_t)(2 * DIMF * 4)), "r"(mb)
                : "memory");
        }
    };

    if (tid == 0) {
        stage(p0, 0, 0);        // A first half
        stage(p0, 1, 1);        // A second half
        stage(p1, 0, 2);        // B first half (prefetch)
    }

    const int fr = lane >> 2;                    // fragment row 0..7
    const int ft = lane & 3;                     // fragment k 0..3

    float d1[4] = {0.f, 0.f, 0.f, 0.f};          // cols 0..7
    float d2[4] = {0.f, 0.f, 0.f, 0.f};          // cols 8..15

    // compute one identity's gram from buffers (bf = first half, bs = second)
    auto compute = [&](int bf, int bs) {
        const float* F = smf + bf * (BUF_BYTES / 4) + foff(fr) + w * 256 + ft;
        const float* S = smf + bs * (BUF_BYTES / 4) + foff(fr) + w * 256 + ft;
        #pragma unroll
        for (int s = 0; s < 32; s++) {
            uint32_t a0 = __float_as_uint(F[s * 8]);
            uint32_t a2 = __float_as_uint(F[s * 8 + 4]);
            uint32_t a1 = __float_as_uint(S[s * 8]);
            uint32_t a3 = __float_as_uint(S[s * 8 + 4]);
            MMA_TF32(d1, a0, a1, a2, a3, a0, a2);   // B = rows 0..7
            MMA_TF32(d2, a0, a1, a2, a3, a1, a3);   // B = rows 8..15
        }
    };

    auto flush = [&](float (*gram)[GROUP]) {
        const int rr = lane >> 2;
        const int cc = 2 * (lane & 3);
        atomicAdd(&gram[rr][cc],             d1[0]);
        atomicAdd(&gram[rr][cc + 1],         d1[1]);
        atomicAdd(&gram[rr + 8][cc],         d1[2]);
        atomicAdd(&gram[rr + 8][cc + 1],     d1[3]);
        atomicAdd(&gram[rr][8 + cc],         d2[0]);
        atomicAdd(&gram[rr][8 + cc + 1],     d2[1]);
        atomicAdd(&gram[rr + 8][8 + cc],     d2[2]);
        atomicAdd(&gram[rr + 8][8 + cc + 1], d2[3]);
    };

    // ---- identity A ----
    mbar_wait(mbb + 0u, 0u);
    mbar_wait(mbb + 8u, 0u);
    compute(0, 1);
    flush(gramA);
    __syncthreads();                 // all warps done reading buf0/buf1
    if (tid == 0) stage(p1, 1, 0);   // B second half -> buf0 (phase 1)

    // ---- identity B ----
    #pragma unroll
    for (int i = 0; i < 4; i++) { d1[i] = 0.f; d2[i] = 0.f; }
    mbar_wait(mbb + 16u, 0u);
    mbar_wait(mbb + 0u, 1u);
    compute(2, 0);
    flush(gramB);
    __syncthreads();

    // ---- mins + loss: warp 0 -> gramA, warp 1 -> gramB ----
    if (w < 2) {
        float (*gram)[GROUP] = (w == 0) ? gramA : gramB;
        const int r = lane & 15;
        float inv = 1.0f / (sqrtf(gram[r][r]) + 1e-10f);
        float minf = INFINITY, mins = INFINITY;
        #pragma unroll
        for (int c = 0; c < GROUP; c++) {
            float invc = __shfl_sync(0xffffffffu, inv, c);
            float v = gram[r][c] * inv * invc;
            if (c < KIDS) minf = fminf(minf, v);
            else          mins = fminf(mins, v);
        }
        float li = fmaxf(MARGIN - minf, 0.0f) + fmaxf(MARGIN - mins, 0.0f);
        if (lane >= 16) li = 0.0f;
        #pragma unroll
        for (int o = 16; o; o >>= 1)
            li += __shfl_xor_sync(0xffffffffu, li, o);
        if (lane == 0)
            atomicAdd(out, li);
    }
}

extern "C" void kernel_launch(void* const* d_in, const int* in_sizes, int n_in,
                              void* d_out, int out_size)
{
    const float* x = (const float*)d_in[0];
    float* out = (float*)d_out;

    cudaMemsetAsync(out, 0, sizeof(float), 0);

    static bool attr_set = false;
    if (!attr_set) {
        cudaFuncSetAttribute(wloss_kernel,
                             cudaFuncAttributeMaxDynamicSharedMemorySize,
                             SMEM_BYTES);
        attr_set = true;
    }

    wloss_kernel<<<GRID, THREADS, SMEM_BYTES>>>(x, out);
}

// round 8
// speedup vs baseline: 1.0349x; 1.0349x over previous
#include <cuda_runtime.h>
#include <math.h>
#include <stdint.h>

// Problem constants (match reference setup_inputs)
#define DIMF     2048
#define KIDS     8
#define P        256
#define HALF     2048
#define MARGIN   1.0f

#define THREADS  256
#define GROUP    16                    // rows per identity (2*K)
#define CHUNK    512                   // K floats per chunk
#define NCHUNK   (DIMF / CHUNK)        // 4
#define CH_F4    (CHUNK / 4)           // 128 float4 per row per chunk
#define STRIDE_F 516                   // padded smem row stride (floats)
#define STRIDE_F4 (STRIDE_F / 4)       // 129
#define BUF_F4   (GROUP * STRIDE_F4)   // 2064 float4 per buffer
#define SMEM_BYTES (2 * BUF_F4 * 16)   // 66048 (double buffer)

// D(16x8) += A(16x8) * B(8x8), tf32. Gram trick: B fragments are A fragments.
#define MMA_TF32(d, a0, a1, a2, a3, b0, b1)                                \
    asm volatile(                                                          \
        "mma.sync.aligned.m16n8k8.row.col.f32.tf32.tf32.f32 "              \
        "{%0,%1,%2,%3}, {%4,%5,%6,%7}, {%8,%9}, {%0,%1,%2,%3};"            \
        : "+f"(d[0]), "+f"(d[1]), "+f"(d[2]), "+f"(d[3])                   \
        : "r"(a0), "r"(a1), "r"(a2), "r"(a3), "r"(b0), "r"(b1))

__global__ __launch_bounds__(THREADS, 2)
void wloss_kernel(const float* __restrict__ x, float* __restrict__ out)
{
    extern __shared__ float smf[];               // [2][16][STRIDE_F]
    float4* smf4 = reinterpret_cast<float4*>(smf);
    __shared__ float gram[GROUP][GROUP];

    const int p    = blockIdx.x;                 // identity
    const int tid  = threadIdx.x;
    const int w    = tid >> 5;                   // warp 0..7 (K split)
    const int lane = tid & 31;

    if (tid < GROUP * GROUP)
        gram[tid >> 4][tid & 15] = 0.0f;

    const float4* x4 = reinterpret_cast<const float4*>(x);

    // staging helpers: thread handles 8 float4 per chunk, fully coalesced
    float4 ra[8], rb[8];
    auto ldg_chunk = [&](float4* r, int ch) {
        #pragma unroll
        for (int j = 0; j < 8; j++) {
            int i   = j * THREADS + tid;
            int row = i >> 7;                    // 0..15
            int c4  = i & (CH_F4 - 1);
            int grow = (row < KIDS) ? (p * KIDS + row)
                                    : (HALF + p * KIDS + (row - KIDS));
            r[j] = __ldg(&x4[(size_t)grow * (DIMF / 4) + ch * CH_F4 + c4]);
        }
    };
    auto sts_chunk = [&](const float4* r, int b) {
        #pragma unroll
        for (int j = 0; j < 8; j++) {
            int i   = j * THREADS + tid;
            int row = i >> 7;
            int c4  = i & (CH_F4 - 1);
            smf4[b * BUF_F4 + row * STRIDE_F4 + c4] = r[j];
        }
    };

    // MMA fragment indexing
    const int fr = lane >> 2;                    // fragment row 0..7
    const int ft = lane & 3;                     // fragment k 0..3
    float d1[4] = {0.f, 0.f, 0.f, 0.f};          // cols 0..7
    float d2[4] = {0.f, 0.f, 0.f, 0.f};          // cols 8..15

    auto compute = [&](int b) {                  // warp w: K-slab [w*64,+64)
        const float* b0p = smf + b * (BUF_F4 * 4) + fr * STRIDE_F + w * 64 + ft;
        const float* b1p = b0p + 8 * STRIDE_F;
        #pragma unroll
        for (int s = 0; s < 8; s++) {
            uint32_t a0 = __float_as_uint(b0p[s * 8]);
            uint32_t a2 = __float_as_uint(b0p[s * 8 + 4]);
            uint32_t a1 = __float_as_uint(b1p[s * 8]);
            uint32_t a3 = __float_as_uint(b1p[s * 8 + 4]);
            MMA_TF32(d1, a0, a1, a2, a3, a0, a2);   // B = rows 0..7
            MMA_TF32(d2, a0, a1, a2, a3, a1, a3);   // B = rows 8..15
        }
    };

    // ---- pipelined stream: regs hold chunk+1/+2 while smem holds chunk ----
    ldg_chunk(ra, 0);
    ldg_chunk(rb, 1);
    sts_chunk(ra, 0);
    __syncthreads();

    #pragma unroll
    for (int ch = 0; ch < NCHUNK; ch++) {
        compute(ch & 1);
        if (ch + 1 < NCHUNK)
            sts_chunk((ch & 1) ? ra : rb, (ch + 1) & 1);   // chunk ch+1
        if (ch + 2 < NCHUNK)
            ldg_chunk((ch & 1) ? rb : ra, ch + 2);         // refill freed regs
        __syncthreads();
    }

    // ---- reduce 8 warps' partial grams into smem ----
    {
        const int rr = lane >> 2;
        const int cc = 2 * (lane & 3);
        atomicAdd(&gram[rr][cc],             d1[0]);
        atomicAdd(&gram[rr][cc + 1],         d1[1]);
        atomicAdd(&gram[rr + 8][cc],         d1[2]);
        atomicAdd(&gram[rr + 8][cc + 1],     d1[3]);
        atomicAdd(&gram[rr][8 + cc],         d2[0]);
        atomicAdd(&gram[rr][8 + cc + 1],     d2[1]);
        atomicAdd(&gram[rr + 8][8 + cc],     d2[2]);
        atomicAdd(&gram[rr + 8][8 + cc + 1], d2[3]);
    }
    __syncthreads();

    // ---- mins + loss (warp 0; diag of gram == squared norms) ----
    if (w == 0) {
        const int r = lane & 15;
        float inv = 1.0f / (sqrtf(gram[r][r]) + 1e-10f);
        float minf = INFINITY, mins = INFINITY;
        #pragma unroll
        for (int c = 0; c < GROUP; c++) {
            float invc = __shfl_sync(0xffffffffu, inv, c);
            float v = gram[r][c] * inv * invc;
            if (c < KIDS) minf = fminf(minf, v);
            else          mins = fminf(mins, v);
        }
        float li = fmaxf(MARGIN - minf, 0.0f) + fmaxf(MARGIN - mins, 0.0f);
        if (lane >= 16) li = 0.0f;
        #pragma unroll
        for (int o = 16; o; o >>= 1)
            li += __shfl_xor_sync(0xffffffffu, li, o);
        if (lane == 0)
            atomicAdd(out, li);
    }
}

extern "C" void kernel_launch(void* const* d_in, const int* in_sizes, int n_in,
                              void* d_out, int out_size)
{
    const float* x = (const float*)d_in[0];
    float* out = (float*)d_out;

    cudaMemsetAsync(out, 0, sizeof(float), 0);

    static bool attr_set = false;
    if (!attr_set) {
        cudaFuncSetAttribute(wloss_kernel,
                             cudaFuncAttributeMaxDynamicSharedMemorySize,
                             SMEM_BYTES);
        attr_set = true;
    }

    wloss_kernel<<<P, THREADS, SMEM_BYTES>>>(x, out);
}